// round 17
// baseline (speedup 1.0000x reference)
#include <cuda_runtime.h>
#include <cuda_bf16.h>
#include <cuda_fp16.h>
#include <math.h>
#include <stdint.h>

#define BATCH 4
#define SEQ   2048
#define CDIM  1024
#define NHEAD 16
#define DHEAD 64
#define MR    (BATCH*SEQ)   /* 8192 rows */

// ---------------- scratch (device globals; no allocation allowed) ----------
__device__ float g_v[(size_t)MR*CDIM];
__device__ __half g_p[(size_t)BATCH*NHEAD*SEQ*SEQ];   // unnormalized exp(S), fp16
__device__ __nv_bfloat16 g_ahi[(size_t)MR*CDIM];
__device__ __nv_bfloat16 g_alo[(size_t)MR*CDIM];
__device__ __nv_bfloat16 g_whi[(size_t)4*CDIM*CDIM];   // W^T hi, 4 matrices
__device__ __nv_bfloat16 g_wlo[(size_t)4*CDIM*CDIM];   // W^T lo
__device__ __nv_bfloat16 g_qhi[(size_t)MR*CDIM];
__device__ __nv_bfloat16 g_qlo[(size_t)MR*CDIM];
__device__ __nv_bfloat16 g_khi[(size_t)MR*CDIM];
__device__ __nv_bfloat16 g_klo[(size_t)MR*CDIM];
__device__ __half g_vthi[(size_t)BATCH*NHEAD*DHEAD*SEQ];
__device__ __half g_vtlo[(size_t)BATCH*NHEAD*DHEAD*SEQ];

// ---------------- PTX helpers ----------------------------------------------
static __device__ __forceinline__ uint32_t smem_u32(const void* p) {
    uint32_t a;
    asm("{ .reg .u64 t; cvta.to.shared.u64 t, %1; cvt.u32.u64 %0, t; }"
        : "=r"(a) : "l"(p));
    return a;
}
static __device__ __forceinline__ void cp_async16(uint32_t dst, const void* src) {
    asm volatile("cp.async.cg.shared.global [%0], [%1], 16;" :: "r"(dst), "l"(src) : "memory");
}
static __device__ __forceinline__ void cp_commit() {
    asm volatile("cp.async.commit_group;" ::: "memory");
}
template <int N> static __device__ __forceinline__ void cp_wait() {
    asm volatile("cp.async.wait_group %0;" :: "n"(N) : "memory");
}
static __device__ __forceinline__ void mma_bf16(float* c, const uint32_t* a, const uint32_t* b) {
    asm volatile(
        "mma.sync.aligned.m16n8k16.row.col.f32.bf16.bf16.f32 "
        "{%0,%1,%2,%3}, {%4,%5,%6,%7}, {%8,%9}, {%0,%1,%2,%3};"
        : "+f"(c[0]), "+f"(c[1]), "+f"(c[2]), "+f"(c[3])
        : "r"(a[0]), "r"(a[1]), "r"(a[2]), "r"(a[3]), "r"(b[0]), "r"(b[1]));
}
static __device__ __forceinline__ void mma_f16(float* c, const uint32_t* a, const uint32_t* b) {
    asm volatile(
        "mma.sync.aligned.m16n8k16.row.col.f32.f16.f16.f32 "
        "{%0,%1,%2,%3}, {%4,%5,%6,%7}, {%8,%9}, {%0,%1,%2,%3};"
        : "+f"(c[0]), "+f"(c[1]), "+f"(c[2]), "+f"(c[3])
        : "r"(a[0]), "r"(a[1]), "r"(a[2]), "r"(a[3]), "r"(b[0]), "r"(b[1]));
}

// fast exp on the FMA pipe (no MUFU): range-reduce + deg-6 poly, rel err ~1e-7
static __device__ __forceinline__ float exp_fast(float x) {
    int ni = __float2int_rn(x * 1.4426950408889634f);
    if (ni < -126) ni = -126;
    float nf = (float)ni;
    float r = fmaf(nf, -6.93145752e-1f, x);
    r = fmaf(nf, -1.42860677e-6f, r);
    float p = 1.3888889e-3f;
    p = fmaf(p, r, 8.3333333e-3f);
    p = fmaf(p, r, 4.1666667e-2f);
    p = fmaf(p, r, 1.6666667e-1f);
    p = fmaf(p, r, 0.5f);
    p = fmaf(p, r, 1.0f);
    p = fmaf(p, r, 1.0f);
    return p * __int_as_float((ni + 127) << 23);
}

// ---------------- HMMA split-bf16 GEMM core ---------------------------------
#define BK      32
#define LDA     40
#define TILE_H  (128*LDA)
#define TILE_B  (TILE_H*2)
#define STAGE_B (4*TILE_B)
#define GSM_TOTAL (2*STAGE_B)
#define NCHUNK  (CDIM/BK)

static __device__ __forceinline__ void gemm_fill(
    uint32_t st, int chunk,
    const __nv_bfloat16* __restrict__ Ahi, const __nv_bfloat16* __restrict__ Alo,
    const __nv_bfloat16* __restrict__ Bhi, const __nv_bfloat16* __restrict__ Blo,
    int m0, int n0, int tid)
{
    const int k0 = chunk << 5;
    #pragma unroll
    for (int t = 0; t < 8; t++) {
        int i = tid + t * 256;
        int tile = i >> 9;
        int idx  = i & 511;
        int r = idx >> 2, j = idx & 3;
        const __nv_bfloat16* base =
            (tile == 0) ? Ahi : (tile == 1) ? Alo : (tile == 2) ? Bhi : Blo;
        int row = ((tile < 2) ? m0 : n0) + r;
        cp_async16(st + tile * TILE_B + r * (LDA*2) + j * 16,
                   base + (size_t)row * CDIM + k0 + (j << 3));
    }
    cp_commit();
}

// computes acc for a 128x128 tile at (m0, n0); shared by both gemm kernels
static __device__ __forceinline__ void gemm_core(
    uint32_t sb, __nv_bfloat16* smem,
    const __nv_bfloat16* Ahi, const __nv_bfloat16* Alo,
    const __nv_bfloat16* Bhi, const __nv_bfloat16* Blo,
    int m0, int n0, int tid, float acc[2][8][4])
{
    const int warp = tid >> 5;
    const int lane = tid & 31;
    const int wm = warp & 3, wn = warp >> 2;
    const int a_row0 = wm * 32;
    const int b_col0 = wn * 64;
    const int lr = lane >> 2;
    const int lc = (lane & 3) << 1;

    gemm_fill(sb,           0, Ahi, Alo, Bhi, Blo, m0, n0, tid);
    gemm_fill(sb + STAGE_B, 1, Ahi, Alo, Bhi, Blo, m0, n0, tid);

    for (int c = 0; c < NCHUNK; c++) {
        const __nv_bfloat16* st = smem + (size_t)(c & 1) * (STAGE_B/2);
        if (c < NCHUNK - 1) cp_wait<1>(); else cp_wait<0>();
        __syncthreads();

        const __nv_bfloat16* sAhi = st;
        const __nv_bfloat16* sAlo = st + TILE_H;
        const __nv_bfloat16* sBhi = st + 2*TILE_H;
        const __nv_bfloat16* sBlo = st + 3*TILE_H;

        #pragma unroll
        for (int ks = 0; ks < 2; ks++) {
            const int kh = ks * 16;
            uint32_t fahi[2][4], falo[2][4];
            #pragma unroll
            for (int mt = 0; mt < 2; mt++) {
                const int r0 = a_row0 + mt*16 + lr;
                const __nv_bfloat16* p0 = sAhi + r0*LDA + kh + lc;
                const __nv_bfloat16* p1 = sAlo + r0*LDA + kh + lc;
                fahi[mt][0] = *(const uint32_t*)(p0);
                fahi[mt][1] = *(const uint32_t*)(p0 + 8*LDA);
                fahi[mt][2] = *(const uint32_t*)(p0 + 8);
                fahi[mt][3] = *(const uint32_t*)(p0 + 8*LDA + 8);
                falo[mt][0] = *(const uint32_t*)(p1);
                falo[mt][1] = *(const uint32_t*)(p1 + 8*LDA);
                falo[mt][2] = *(const uint32_t*)(p1 + 8);
                falo[mt][3] = *(const uint32_t*)(p1 + 8*LDA + 8);
            }
            #pragma unroll
            for (int nt = 0; nt < 8; nt++) {
                const int nr = b_col0 + nt*8 + lr;
                const __nv_bfloat16* q0 = sBhi + nr*LDA + kh + lc;
                const __nv_bfloat16* q1 = sBlo + nr*LDA + kh + lc;
                uint32_t fbhi[2], fblo[2];
                fbhi[0] = *(const uint32_t*)(q0);
                fbhi[1] = *(const uint32_t*)(q0 + 8);
                fblo[0] = *(const uint32_t*)(q1);
                fblo[1] = *(const uint32_t*)(q1 + 8);
                #pragma unroll
                for (int mt = 0; mt < 2; mt++) {
                    mma_bf16(acc[mt][nt], fahi[mt], fbhi);
                    mma_bf16(acc[mt][nt], fahi[mt], fblo);
                    mma_bf16(acc[mt][nt], falo[mt], fbhi);
                }
            }
        }
        __syncthreads();
        if (c + 2 < NCHUNK)
            gemm_fill(sb + (c & 1) * STAGE_B, c + 2, Ahi, Alo, Bhi, Blo, m0, n0, tid);
    }
}

// fused QKV: grid.x = 24 (8 per matrix), grid.y = 64
__global__ void __launch_bounds__(256, 1)
gemm_qkv(const __nv_bfloat16* __restrict__ Ahi, const __nv_bfloat16* __restrict__ Alo,
         const __nv_bfloat16* __restrict__ Whi, const __nv_bfloat16* __restrict__ Wlo,
         const float* __restrict__ bq, const float* __restrict__ bk,
         const float* __restrict__ bv,
         __nv_bfloat16* __restrict__ qhi, __nv_bfloat16* __restrict__ qlo,
         __nv_bfloat16* __restrict__ khi, __nv_bfloat16* __restrict__ klo,
         float* __restrict__ vout)
{
    extern __shared__ __nv_bfloat16 smem[];
    const uint32_t sb = smem_u32(smem);
    const int tid  = threadIdx.x;
    const int mat  = blockIdx.x >> 3;             // 0=q 1=k 2=v
    const int n0   = (blockIdx.x & 7) << 7;
    const int m0   = blockIdx.y << 7;
    const size_t WSZ = (size_t)CDIM * CDIM;
    const __nv_bfloat16* Bh = Whi + (size_t)mat * WSZ;
    const __nv_bfloat16* Bl = Wlo + (size_t)mat * WSZ;
    const float* bias = (mat == 0) ? bq : (mat == 1) ? bk : bv;

    float acc[2][8][4];
    #pragma unroll
    for (int mt = 0; mt < 2; mt++)
        #pragma unroll
        for (int nt = 0; nt < 8; nt++)
            #pragma unroll
            for (int r = 0; r < 4; r++) acc[mt][nt][r] = 0.f;

    gemm_core(sb, smem, Ahi, Alo, Bh, Bl, m0, n0, tid, acc);

    const int warp = tid >> 5, lane = tid & 31;
    const int wm = warp & 3, wn = warp >> 2;
    const int lr = lane >> 2, lc = (lane & 3) << 1;
    __nv_bfloat16* Ohi = (mat == 0) ? qhi : khi;
    __nv_bfloat16* Olo = (mat == 0) ? qlo : klo;

    #pragma unroll
    for (int mt = 0; mt < 2; mt++) {
        const int grow = m0 + wm*32 + mt*16 + lr;
        #pragma unroll
        for (int nt = 0; nt < 8; nt++) {
            const int gcol = n0 + wn*64 + nt*8 + lc;
            float v[4];
            v[0] = acc[mt][nt][0] + bias[gcol];
            v[1] = acc[mt][nt][1] + bias[gcol + 1];
            v[2] = acc[mt][nt][2] + bias[gcol];
            v[3] = acc[mt][nt][3] + bias[gcol + 1];
            if (mat == 2) {
                *(float2*)(vout + (size_t)grow * CDIM + gcol)       = make_float2(v[0], v[1]);
                *(float2*)(vout + (size_t)(grow + 8) * CDIM + gcol) = make_float2(v[2], v[3]);
            } else {
                __nv_bfloat16 h[4], l[4];
                #pragma unroll
                for (int z = 0; z < 4; z++) {
                    h[z] = __float2bfloat16(v[z]);
                    l[z] = __float2bfloat16(v[z] - __bfloat162float(h[z]));
                }
                *(__nv_bfloat162*)(Ohi + (size_t)grow*CDIM + gcol)     = *(__nv_bfloat162*)&h[0];
                *(__nv_bfloat162*)(Ohi + (size_t)(grow+8)*CDIM + gcol) = *(__nv_bfloat162*)&h[2];
                *(__nv_bfloat162*)(Olo + (size_t)grow*CDIM + gcol)     = *(__nv_bfloat162*)&l[0];
                *(__nv_bfloat162*)(Olo + (size_t)(grow+8)*CDIM + gcol) = *(__nv_bfloat162*)&l[2];
            }
        }
    }
}

// Wo projection (fp32 out)
__global__ void __launch_bounds__(256, 1)
gemm_hmma(const __nv_bfloat16* __restrict__ Ahi, const __nv_bfloat16* __restrict__ Alo,
          const __nv_bfloat16* __restrict__ Bhi, const __nv_bfloat16* __restrict__ Blo,
          const float* __restrict__ bias, float* __restrict__ O)
{
    extern __shared__ __nv_bfloat16 smem[];
    const uint32_t sb = smem_u32(smem);
    const int tid  = threadIdx.x;
    const int n0 = blockIdx.x << 7;
    const int m0 = blockIdx.y << 7;

    float acc[2][8][4];
    #pragma unroll
    for (int mt = 0; mt < 2; mt++)
        #pragma unroll
        for (int nt = 0; nt < 8; nt++)
            #pragma unroll
            for (int r = 0; r < 4; r++) acc[mt][nt][r] = 0.f;

    gemm_core(sb, smem, Ahi, Alo, Bhi, Blo, m0, n0, tid, acc);

    const int warp = tid >> 5, lane = tid & 31;
    const int wm = warp & 3, wn = warp >> 2;
    const int lr = lane >> 2, lc = (lane & 3) << 1;
    #pragma unroll
    for (int mt = 0; mt < 2; mt++) {
        const int grow = m0 + wm*32 + mt*16 + lr;
        #pragma unroll
        for (int nt = 0; nt < 8; nt++) {
            const int gcol = n0 + wn*64 + nt*8 + lc;
            *(float2*)(O + (size_t)grow * CDIM + gcol) =
                make_float2(acc[mt][nt][0] + bias[gcol], acc[mt][nt][1] + bias[gcol+1]);
            *(float2*)(O + (size_t)(grow + 8) * CDIM + gcol) =
                make_float2(acc[mt][nt][2] + bias[gcol], acc[mt][nt][3] + bias[gcol+1]);
        }
    }
}

// ---------------- conversion kernels ---------------------------------------
__global__ void __launch_bounds__(256)
split_f32(const float* __restrict__ in, __nv_bfloat16* __restrict__ hi,
          __nv_bfloat16* __restrict__ lo)
{
    size_t i = (size_t)blockIdx.x * 256 + threadIdx.x;
    float4 v = ((const float4*)in)[i];
    float f[4] = {v.x, v.y, v.z, v.w};
    __nv_bfloat16 h[4], l[4];
    #pragma unroll
    for (int j = 0; j < 4; j++) {
        h[j] = __float2bfloat16(f[j]);
        l[j] = __float2bfloat16(f[j] - __bfloat162float(h[j]));
    }
    ((uint2*)hi)[i] = *(uint2*)h;
    ((uint2*)lo)[i] = *(uint2*)l;
}

__global__ void __launch_bounds__(256)
transpose_split(const float* __restrict__ W, __nv_bfloat16* __restrict__ Thi,
                __nv_bfloat16* __restrict__ Tlo)
{
    __shared__ float ts[32][33];
    const int tx = threadIdx.x & 31, ty = threadIdx.x >> 5;
    const int bx = blockIdx.x << 5;
    const int by = blockIdx.y << 5;
    #pragma unroll
    for (int dy = 0; dy < 4; dy++)
        ts[ty + dy * 8][tx] = W[(size_t)(by + ty + dy * 8) * CDIM + bx + tx];
    __syncthreads();
    #pragma unroll
    for (int dy = 0; dy < 4; dy++) {
        float v = ts[tx][ty + dy * 8];
        __nv_bfloat16 h = __float2bfloat16(v);
        __nv_bfloat16 l = __float2bfloat16(v - __bfloat162float(h));
        size_t o = (size_t)(bx + ty + dy * 8) * CDIM + by + tx;
        Thi[o] = h;
        Tlo[o] = l;
    }
}

// v fp32 [ (b*2048+t), h*64+d ] -> vt fp16 hi/lo [hn][d][t]
__global__ void __launch_bounds__(256)
vt_split(const float* __restrict__ v, __half* __restrict__ vthi,
         __half* __restrict__ vtlo)
{
    __shared__ float ts[32][33];
    const int tx = threadIdx.x & 31, ty = threadIdx.x >> 5;
    const int t0 = blockIdx.x << 5;
    const int d0 = blockIdx.y << 5;
    const int hn = blockIdx.z;
    const int b = hn >> 4, h = hn & 15;
    #pragma unroll
    for (int k = 0; k < 4; k++)
        ts[ty + k*8][tx] = v[(size_t)(b*SEQ + t0 + ty + k*8) * CDIM + h*64 + d0 + tx];
    __syncthreads();
    #pragma unroll
    for (int k = 0; k < 4; k++) {
        float val = ts[tx][ty + k*8];
        __half hh = __float2half(val);
        __half ll = __float2half(val - __half2float(hh));
        size_t o = ((size_t)hn * DHEAD + d0 + ty + k*8) * SEQ + t0 + tx;
        vthi[o] = hh;
        vtlo[o] = ll;
    }
}

// ---------------- fused single-pass attention --------------------------------
// smem byte layout (dynamic):
//   Qhi @ 0, Qlo @ 18432                                    (36864)
//   K stage s @ 36864 + s*36864 : Khi, Klo (18432 each)     (73728)
//   V stage s @ 110592 + s*34816 : Vhi, Vlo (17408 each)    (69632)
//   P tile fp16 @ 180224 : 128 x 136 halves                 (34816)
#define SLD   72
#define VLD   136
#define PLD   136
#define OFF_QLO 18432
#define OFF_K   36864
#define KSTG    36864
#define OFF_V   110592
#define VSTG    34816
#define OFF_P   180224
#define ASM_TOTAL 215040

static __device__ __forceinline__ void fill_kv(
    uint32_t sb, int s, int kt,
    const __nv_bfloat16* __restrict__ gkh, const __nv_bfloat16* __restrict__ gkl,
    const __half* __restrict__ gvh, const __half* __restrict__ gvl, int tid)
{
    const int row0 = kt << 7;
    const uint32_t kb = sb + OFF_K + s * KSTG;
    #pragma unroll
    for (int t = 0; t < 8; t++) {
        int i = tid + t * 256;
        int which = i >> 10, e = i & 1023;
        int r = e >> 3, c8 = e & 7;
        cp_async16(kb + (which ? 18432 : 0) + (r*SLD + (c8 << 3)) * 2,
                   (which ? gkl : gkh) + (size_t)(row0 + r)*CDIM + (c8 << 3));
    }
    const uint32_t vb = sb + OFF_V + s * VSTG;
    #pragma unroll
    for (int t = 0; t < 8; t++) {
        int i = tid + t * 256;
        int which = i >> 10, e = i & 1023;
        int d = e >> 4, c8 = e & 15;
        cp_async16(vb + (which ? 17408 : 0) + (d*VLD + (c8 << 3)) * 2,
                   (which ? gvl : gvh) + (size_t)d*SEQ + row0 + (c8 << 3));
    }
    cp_commit();
}

__global__ void __launch_bounds__(256, 1)
attn_fused(const __nv_bfloat16* __restrict__ qhi, const __nv_bfloat16* __restrict__ qlo,
           const __nv_bfloat16* __restrict__ khi, const __nv_bfloat16* __restrict__ klo,
           const __half* __restrict__ vthi, const __half* __restrict__ vtlo,
           __half* __restrict__ pexp, float* __restrict__ wts,
           __nv_bfloat16* __restrict__ ohi, __nv_bfloat16* __restrict__ olo)
{
    extern __shared__ char smc[];
    __shared__ float red[128][2];
    __shared__ float linv[128];
    const uint32_t sb = smem_u32(smc);
    const int tid  = threadIdx.x;
    const int warp = tid >> 5;
    const int lane = tid & 31;
    const int wm = warp & 3, wn = warp >> 2;
    const int lr = lane >> 2, lc = (lane & 3) << 1;

    const int qt = 15 - (blockIdx.x & 15);
    const int hn = blockIdx.x >> 4;
    const int b = hn >> 4, h = hn & 15;
    const int q0 = qt << 7;

    const __nv_bfloat16* gqh = qhi + (size_t)b*SEQ*CDIM + h*64;
    const __nv_bfloat16* gql = qlo + (size_t)b*SEQ*CDIM + h*64;
    const __nv_bfloat16* gkh = khi + (size_t)b*SEQ*CDIM + h*64;
    const __nv_bfloat16* gkl = klo + (size_t)b*SEQ*CDIM + h*64;
    const __half* gvh = vthi + (size_t)hn * DHEAD * SEQ;
    const __half* gvl = vtlo + (size_t)hn * DHEAD * SEQ;
    __half* prow = pexp + (size_t)hn * SEQ * SEQ;
    float* wrow = wts + (size_t)hn * SEQ * SEQ;

    const __nv_bfloat16* sQh = (const __nv_bfloat16*)(smc);
    const __nv_bfloat16* sQl = (const __nv_bfloat16*)(smc + OFF_QLO);
    __half* sP = (__half*)(smc + OFF_P);

    // prologue: Q + {K0,V0} in group 0, {K1,V1} in group 1
    #pragma unroll
    for (int t = 0; t < 8; t++) {
        int i = tid + t * 256;
        int which = i >> 10, e = i & 1023;
        int r = e >> 3, c8 = e & 7;
        cp_async16(sb + (which ? OFF_QLO : 0) + (r*SLD + (c8 << 3)) * 2,
                   (which ? gql : gqh) + (size_t)(q0 + r)*CDIM + (c8 << 3));
    }
    fill_kv(sb, 0, 0, gkh, gkl, gvh, gvl, tid);
    if (qt >= 1) fill_kv(sb, 1, 1, gkh, gkl, gvh, gvl, tid);

    float psum[4] = {0.f, 0.f, 0.f, 0.f};
    float acco[2][4][4];
    #pragma unroll
    for (int mt = 0; mt < 2; mt++)
        #pragma unroll
        for (int nt = 0; nt < 4; nt++)
            #pragma unroll
            for (int r = 0; r < 4; r++) acco[mt][nt][r] = 0.f;

    for (int kt = 0; kt <= qt; kt++) {
        if (kt + 1 <= qt) cp_wait<1>(); else cp_wait<0>();
        __syncthreads();

        const int s = kt & 1;
        const __nv_bfloat16* Kh = (const __nv_bfloat16*)(smc + OFF_K + s*KSTG);
        const __nv_bfloat16* Kl = (const __nv_bfloat16*)(smc + OFF_K + s*KSTG + 18432);
        const __half* Vh = (const __half*)(smc + OFF_V + s*VSTG);
        const __half* Vl = (const __half*)(smc + OFF_V + s*VSTG + 17408);

        // ---- S = Q @ K^T (3-product bf16) ----
        float acc[2][8][4];
        #pragma unroll
        for (int mt = 0; mt < 2; mt++)
            #pragma unroll
            for (int nt = 0; nt < 8; nt++)
                #pragma unroll
                for (int r = 0; r < 4; r++) acc[mt][nt][r] = 0.f;

        #pragma unroll
        for (int ks = 0; ks < 4; ks++) {
            const int kh = ks * 16;
            uint32_t fahi[2][4], falo[2][4];
            #pragma unroll
            for (int mt = 0; mt < 2; mt++) {
                const int r0 = wm*32 + mt*16 + lr;
                const __nv_bfloat16* p0 = sQh + r0*SLD + kh + lc;
                const __nv_bfloat16* p1 = sQl + r0*SLD + kh + lc;
                fahi[mt][0] = *(const uint32_t*)(p0);
                fahi[mt][1] = *(const uint32_t*)(p0 + 8*SLD);
                fahi[mt][2] = *(const uint32_t*)(p0 + 8);
                fahi[mt][3] = *(const uint32_t*)(p0 + 8*SLD + 8);
                falo[mt][0] = *(const uint32_t*)(p1);
                falo[mt][1] = *(const uint32_t*)(p1 + 8*SLD);
                falo[mt][2] = *(const uint32_t*)(p1 + 8);
                falo[mt][3] = *(const uint32_t*)(p1 + 8*SLD + 8);
            }
            #pragma unroll
            for (int nt = 0; nt < 8; nt++) {
                const int nr = wn*64 + nt*8 + lr;
                const __nv_bfloat16* pk0 = Kh + nr*SLD + kh + lc;
                const __nv_bfloat16* pk1 = Kl + nr*SLD + kh + lc;
                uint32_t fbhi[2], fblo[2];
                fbhi[0] = *(const uint32_t*)(pk0);
                fbhi[1] = *(const uint32_t*)(pk0 + 8);
                fblo[0] = *(const uint32_t*)(pk1);
                fblo[1] = *(const uint32_t*)(pk1 + 8);
                #pragma unroll
                for (int mt = 0; mt < 2; mt++) {
                    mma_bf16(acc[mt][nt], fahi[mt], fbhi);
                    mma_bf16(acc[mt][nt], fahi[mt], fblo);
                    mma_bf16(acc[mt][nt], falo[mt], fbhi);
                }
            }
        }

        // ---- epilogue: exp, rowsum, P -> gmem + smem ----
        #pragma unroll
        for (int mt = 0; mt < 2; mt++) {
            const int rl0 = wm*32 + mt*16 + lr;
            const int grow0 = q0 + rl0, grow1 = grow0 + 8;
            #pragma unroll
            for (int nt = 0; nt < 8; nt++) {
                const int cl = wn*64 + nt*8 + lc;
                const int gcol = (kt << 7) + cl;
                float e00 = (gcol     <= grow0) ? exp_fast(acc[mt][nt][0] * 0.125f) : 0.f;
                float e01 = (gcol + 1 <= grow0) ? exp_fast(acc[mt][nt][1] * 0.125f) : 0.f;
                float e10 = (gcol     <= grow1) ? exp_fast(acc[mt][nt][2] * 0.125f) : 0.f;
                float e11 = (gcol + 1 <= grow1) ? exp_fast(acc[mt][nt][3] * 0.125f) : 0.f;
                psum[mt*2 + 0] += e00 + e01;
                psum[mt*2 + 1] += e10 + e11;
                __half2 p0 = __floats2half2_rn(e00, e01);
                __half2 p1 = __floats2half2_rn(e10, e11);
                *(uint32_t*)(prow + (size_t)grow0*SEQ + gcol) = *(uint32_t*)&p0;
                *(uint32_t*)(prow + (size_t)grow1*SEQ + gcol) = *(uint32_t*)&p1;
                *(uint32_t*)(sP + rl0*PLD + cl)       = *(uint32_t*)&p0;
                *(uint32_t*)(sP + (rl0 + 8)*PLD + cl) = *(uint32_t*)&p1;
            }
        }
        __syncthreads();   // P tile visible

        // ---- O += P @ V (2-product fp16, P from smem) ----
        #pragma unroll
        for (int ks = 0; ks < 8; ks++) {
            uint32_t fp[2][4];
            #pragma unroll
            for (int mt = 0; mt < 2; mt++) {
                const int r0 = wm*32 + mt*16 + lr;
                const __half* pr = sP + r0*PLD + ks*16 + lc;
                fp[mt][0] = *(const uint32_t*)(pr);
                fp[mt][1] = *(const uint32_t*)(pr + 8*PLD);
                fp[mt][2] = *(const uint32_t*)(pr + 8);
                fp[mt][3] = *(const uint32_t*)(pr + 8*PLD + 8);
            }
            #pragma unroll
            for (int nt = 0; nt < 4; nt++) {
                const int nr = wn*32 + nt*8 + lr;
                const __half* pv0 = Vh + nr*VLD + ks*16 + lc;
                const __half* pv1 = Vl + nr*VLD + ks*16 + lc;
                uint32_t fbhi[2], fblo[2];
                fbhi[0] = *(const uint32_t*)(pv0);
                fbhi[1] = *(const uint32_t*)(pv0 + 8);
                fblo[0] = *(const uint32_t*)(pv1);
                fblo[1] = *(const uint32_t*)(pv1 + 8);
                #pragma unroll
                for (int mt = 0; mt < 2; mt++) {
                    mma_f16(acco[mt][nt], fp[mt], fbhi);
                    mma_f16(acco[mt][nt], fp[mt], fblo);
                }
            }
        }
        __syncthreads();   // done with K/V stage + P tile

        if (kt + 2 <= qt) fill_kv(sb, s, kt + 2, gkh, gkl, gvh, gvl, tid);
    }

    // ---- row sums -> linv in smem ----
    #pragma unroll
    for (int t = 0; t < 4; t++) {
        psum[t] += __shfl_xor_sync(0xffffffff, psum[t], 1);
        psum[t] += __shfl_xor_sync(0xffffffff, psum[t], 2);
    }
    if ((lane & 3) == 0) {
        #pragma unroll
        for (int t = 0; t < 4; t++)
            red[wm*32 + (t >> 1)*16 + (t & 1)*8 + lr][wn] = psum[t];
    }
    __syncthreads();
    if (tid < 128) linv[tid] = 1.f / (red[tid][0] + red[tid][1]);
    __syncthreads();

    // ---- O epilogue: scale by linv, write bf16 hi/lo ----
    #pragma unroll
    for (int mt = 0; mt < 2; mt++) {
        const int rl = wm*32 + mt*16 + lr;
        const float li0 = linv[rl], li1 = linv[rl + 8];
        const int grow = q0 + rl;
        #pragma unroll
        for (int nt = 0; nt < 4; nt++) {
            const int d = wn*32 + nt*8 + lc;
            const size_t o0 = (size_t)(b*SEQ + grow) * CDIM + h*64 + d;
            const size_t o1 = (size_t)(b*SEQ + grow + 8) * CDIM + h*64 + d;
            float v[4];
            v[0] = acco[mt][nt][0] * li0;
            v[1] = acco[mt][nt][1] * li0;
            v[2] = acco[mt][nt][2] * li1;
            v[3] = acco[mt][nt][3] * li1;
            __nv_bfloat16 hh[4], ll[4];
            #pragma unroll
            for (int z = 0; z < 4; z++) {
                hh[z] = __float2bfloat16(v[z]);
                ll[z] = __float2bfloat16(v[z] - __bfloat162float(hh[z]));
            }
            *(__nv_bfloat162*)(ohi + o0) = *(__nv_bfloat162*)&hh[0];
            *(__nv_bfloat162*)(ohi + o1) = *(__nv_bfloat162*)&hh[2];
            *(__nv_bfloat162*)(olo + o0) = *(__nv_bfloat162*)&ll[0];
            *(__nv_bfloat162*)(olo + o1) = *(__nv_bfloat162*)&ll[2];
        }
    }

    // ---- normalized weights + upper-triangle zeros (P re-read is L2-hot) ----
    {
        const int ncol4 = (q0 + 128) >> 2;
        for (int r = warp; r < 128; r += 8) {
            const __half* ps = prow + (size_t)(q0 + r) * SEQ;
            float* wd = wrow + (size_t)(q0 + r) * SEQ;
            const float li = linv[r];
            for (int c4 = lane; c4 < ncol4; c4 += 32) {
                uint2 raw = *(const uint2*)(ps + (c4 << 2));
                float2 f0 = __half22float2(*(__half2*)&raw.x);
                float2 f1 = __half22float2(*(__half2*)&raw.y);
                float4 o = make_float4(f0.x*li, f0.y*li, f1.x*li, f1.y*li);
                *(float4*)(wd + (c4 << 2)) = o;
            }
            for (int c4 = ncol4 + lane; c4 < (SEQ >> 2); c4 += 32)
                *(float4*)(wd + (c4 << 2)) = make_float4(0.f, 0.f, 0.f, 0.f);
        }
    }
}

// ---------------------------------------------------------------------------
extern "C" void kernel_launch(void* const* d_in, const int* in_sizes, int n_in,
                              void* d_out, int out_size)
{
    const float* x  = (const float*)d_in[0];
    const float* Wq = (const float*)d_in[1];
    const float* bq = (const float*)d_in[2];
    const float* Wk = (const float*)d_in[3];
    const float* bk = (const float*)d_in[4];
    const float* Wv = (const float*)d_in[5];
    const float* bv = (const float*)d_in[6];
    const float* Wo = (const float*)d_in[7];
    const float* bo = (const float*)d_in[8];

    float* out = (float*)d_out;                 // (B,T,C)
    float* wts = out + (size_t)MR * CDIM;       // (B,N,T,T)

    void *pv, *pp, *pahi, *palo, *pwhi, *pwlo;
    void *pqhi, *pqlo, *pkhi, *pklo, *pvthi, *pvtlo;
    cudaGetSymbolAddress(&pv, g_v);
    cudaGetSymbolAddress(&pp, g_p);
    cudaGetSymbolAddress(&pahi, g_ahi);
    cudaGetSymbolAddress(&palo, g_alo);
    cudaGetSymbolAddress(&pwhi, g_whi);
    cudaGetSymbolAddress(&pwlo, g_wlo);
    cudaGetSymbolAddress(&pqhi, g_qhi);
    cudaGetSymbolAddress(&pqlo, g_qlo);
    cudaGetSymbolAddress(&pkhi, g_khi);
    cudaGetSymbolAddress(&pklo, g_klo);
    cudaGetSymbolAddress(&pvthi, g_vthi);
    cudaGetSymbolAddress(&pvtlo, g_vtlo);

    __nv_bfloat16* ahi = (__nv_bfloat16*)pahi;
    __nv_bfloat16* alo = (__nv_bfloat16*)palo;
    __nv_bfloat16* whi = (__nv_bfloat16*)pwhi;
    __nv_bfloat16* wlo = (__nv_bfloat16*)pwlo;
    const size_t WSZ = (size_t)CDIM * CDIM;

    cudaFuncSetAttribute(gemm_qkv, cudaFuncAttributeMaxDynamicSharedMemorySize, GSM_TOTAL);
    cudaFuncSetAttribute(gemm_hmma, cudaFuncAttributeMaxDynamicSharedMemorySize, GSM_TOTAL);
    cudaFuncSetAttribute(attn_fused, cudaFuncAttributeMaxDynamicSharedMemorySize, ASM_TOTAL);

    dim3 tgrid(CDIM/32, CDIM/32);
    transpose_split<<<tgrid, 256>>>(Wq, whi + 0*WSZ, wlo + 0*WSZ);
    transpose_split<<<tgrid, 256>>>(Wk, whi + 1*WSZ, wlo + 1*WSZ);
    transpose_split<<<tgrid, 256>>>(Wv, whi + 2*WSZ, wlo + 2*WSZ);
    transpose_split<<<tgrid, 256>>>(Wo, whi + 3*WSZ, wlo + 3*WSZ);
    split_f32<<<(int)((size_t)MR*CDIM/4/256), 256>>>(x, ahi, alo);

    dim3 qkvgrid(24, MR/128);
    gemm_qkv<<<qkvgrid, 256, GSM_TOTAL>>>(ahi, alo, whi, wlo, bq, bk, bv,
        (__nv_bfloat16*)pqhi, (__nv_bfloat16*)pqlo,
        (__nv_bfloat16*)pkhi, (__nv_bfloat16*)pklo, (float*)pv);

    dim3 vgrid(SEQ/32, DHEAD/32, BATCH*NHEAD);
    vt_split<<<vgrid, 256>>>((const float*)pv, (__half*)pvthi, (__half*)pvtlo);

    const int ablocks = BATCH*NHEAD*(SEQ/128);  // 1024
    attn_fused<<<ablocks, 256, ASM_TOTAL>>>(
        (const __nv_bfloat16*)pqhi, (const __nv_bfloat16*)pqlo,
        (const __nv_bfloat16*)pkhi, (const __nv_bfloat16*)pklo,
        (const __half*)pvthi, (const __half*)pvtlo,
        (__half*)pp, wts, ahi, alo);

    dim3 ggrid(CDIM/128, MR/128);
    gemm_hmma<<<ggrid, 256, GSM_TOTAL>>>(ahi, alo, whi + 3*WSZ, wlo + 3*WSZ, bo, out);
}